// round 4
// baseline (speedup 1.0000x reference)
#include <cuda_runtime.h>
#include <cstddef>

// 7x7 VALID conv, 4096x4096 fp32 -> 4090x4090 fp32, + bias.
// Block 16x8 = 128 threads; tile 128(w) x 32(h) outputs; thread: 4 rows x 8 cols.
// Packed fma.rn.f32x2 with even/odd dual accumulators: every FFMA2 input pair is
// an even-aligned register pair straight from a 128-bit smem load -> zero MOV packs.

#define IN_W 4096
#define IN_H 4096
#define OUT_W 4090
#define OUT_H 4090

#define TILE_W 128
#define TILE_H 32
#define SM_H (TILE_H + 6)   // 38
#define SM_W 136            // 134 needed, padded (544B rows, 16B aligned)

typedef unsigned long long u64;

__device__ __forceinline__ u64 pk(float a, float b) {
    u64 r;
    asm("mov.b64 %0, {%1, %2};" : "=l"(r) : "f"(a), "f"(b));
    return r;
}
__device__ __forceinline__ void upk(u64 v, float &a, float &b) {
    asm("mov.b64 {%0, %1}, %2;" : "=f"(a), "=f"(b) : "l"(v));
}
__device__ __forceinline__ void fma2(u64 &d, u64 a, u64 b) {
    asm("fma.rn.f32x2 %0, %1, %2, %3;" : "=l"(d) : "l"(a), "l"(b), "l"(d));
}

__global__ __launch_bounds__(128)
void conv7x7_kernel(const float* __restrict__ x,
                    const float* __restrict__ w,
                    const float* __restrict__ bias,
                    float* __restrict__ out)
{
    __shared__ float tile[SM_H][SM_W];
    __shared__ u64   wp[49];
    __shared__ float bs;

    const int tx = threadIdx.x;         // 0..15
    const int ty = threadIdx.y;         // 0..7
    const int tid = ty * 16 + tx;       // 0..127

    const int bx = blockIdx.x * TILE_W;
    const int by = blockIdx.y * TILE_H;

    if (tid < 49) { float wv = w[tid]; wp[tid] = pk(wv, wv); }
    if (tid == 49) bs = bias[0];

    // ---- Load input tile (38 x 136 floats, float4 granularity) ----
    #pragma unroll 1
    for (int i = tid; i < SM_H * (SM_W / 4); i += 128) {
        const int r  = i / (SM_W / 4);
        const int c4 = i - r * (SM_W / 4);
        const int gy = by + r;
        const int gx = bx + c4 * 4;
        float4 v = make_float4(0.f, 0.f, 0.f, 0.f);
        if (gy < IN_H) {
            const float* row = x + (size_t)gy * IN_W;
            if (gx + 4 <= IN_W) {
                v = *reinterpret_cast<const float4*>(row + gx);
            } else if (gx < IN_W) {
                v.x = row[gx];
                if (gx + 1 < IN_W) v.y = row[gx + 1];
                if (gx + 2 < IN_W) v.z = row[gx + 2];
            }
        }
        *reinterpret_cast<float4*>(&tile[r][c4 * 4]) = v;
    }
    __syncthreads();

    // ---- Compute: 4 output rows x 8 cols per thread ----
    const int tx8 = tx * 8;        // col base within tile (32B-aligned in smem)
    const int ry  = ty * 4;        // first output row within tile

    // accE[ar][v]: (out[2v],   out[2v+1]) even-dx partials, v=0..3
    // accO[ar][v]: (out[2v-1], out[2v]  ) odd-dx partials,  v=0..4 (lanes -1, 8 garbage)
    u64 accE[4][4];
    u64 accO[4][5];
    #pragma unroll
    for (int a = 0; a < 4; a++) {
        #pragma unroll
        for (int v = 0; v < 4; v++) accE[a][v] = 0ull;
        #pragma unroll
        for (int v = 0; v < 5; v++) accO[a][v] = 0ull;
    }

    #pragma unroll
    for (int r = 0; r < 10; r++) {
        // E[m] = (seg[2m], seg[2m+1]); need m=0..6, load 0..7 via 4x 16B loads
        u64 E[8];
        {
            const ulonglong2* srow =
                reinterpret_cast<const ulonglong2*>(&tile[ry + r][tx8]);
            ulonglong2 q0 = srow[0];
            ulonglong2 q1 = srow[1];
            ulonglong2 q2 = srow[2];
            ulonglong2 q3 = srow[3];
            E[0] = q0.x; E[1] = q0.y;
            E[2] = q1.x; E[3] = q1.y;
            E[4] = q2.x; E[5] = q2.y;
            E[6] = q3.x; E[7] = q3.y;
        }

        #pragma unroll
        for (int ar = 0; ar < 4; ar++) {
            const int kr = r - ar;
            if (kr >= 0 && kr <= 6) {
                // even dx: accE[v] += E[v + dx/2] * (w,w)
                #pragma unroll
                for (int dx = 0; dx <= 6; dx += 2) {
                    const u64 wv = wp[kr * 7 + dx];
                    #pragma unroll
                    for (int v = 0; v < 4; v++)
                        fma2(accE[ar][v], E[v + dx / 2], wv);
                }
                // odd dx: accO[v] += E[v + (dx-1)/2] * (w,w)
                #pragma unroll
                for (int dx = 1; dx <= 5; dx += 2) {
                    const u64 wv = wp[kr * 7 + dx];
                    #pragma unroll
                    for (int v = 0; v < 5; v++)
                        fma2(accO[ar][v], E[v + (dx - 1) / 2], wv);
                }
            }
        }
    }

    // ---- Epilogue: recombine even/odd partials, add bias, store float2 ----
    const float bv = bs;
    #pragma unroll
    for (int ar = 0; ar < 4; ar++) {
        const int oy = by + ry + ar;
        if (oy < OUT_H) {
            float* orow = out + (size_t)oy * OUT_W;
            #pragma unroll
            for (int v = 0; v < 4; v++) {
                const int ox = bx + tx8 + 2 * v;
                if (ox < OUT_W) {
                    float eL, eH, oLoA, oHiA, oLoB, oHiB;
                    upk(accE[ar][v],     eL,   eH);
                    upk(accO[ar][v],     oLoA, oHiA);
                    upk(accO[ar][v + 1], oLoB, oHiB);
                    float2 o;
                    o.x = eL + oHiA + bv;   // out[2v]
                    o.y = eH + oLoB + bv;   // out[2v+1]
                    *reinterpret_cast<float2*>(orow + ox) = o;
                }
            }
        }
    }
}

extern "C" void kernel_launch(void* const* d_in, const int* in_sizes, int n_in,
                              void* d_out, int out_size)
{
    const float* x    = (const float*)d_in[0];
    const float* w    = (const float*)d_in[1];
    const float* bias = (const float*)d_in[2];
    float* out = (float*)d_out;

    dim3 block(16, 8);
    dim3 grid((OUT_W + TILE_W - 1) / TILE_W,   // 32
              (OUT_H + TILE_H - 1) / TILE_H);  // 128
    conv7x7_kernel<<<grid, block>>>(x, w, bias, out);
}

// round 5
// speedup vs baseline: 1.0184x; 1.0184x over previous
#include <cuda_runtime.h>
#include <cstddef>

// 7x7 VALID conv, 4096x4096 fp32 -> 4090x4090 fp32, + bias.
// Block 16x16 = 256 threads; tile 128(w) x 32(h); thread: 2 rows x 8 cols.
// fma.rn.f32x2 with even/odd dual accumulators (zero packing MOVs), and
// kr-major loop order so each weight row is loaded into registers ONCE per
// thread and reused across both accumulator rows (kills LDS->FFMA2 stalls).

#define IN_W 4096
#define IN_H 4096
#define OUT_W 4090
#define OUT_H 4090

#define TILE_W 128
#define TILE_H 32
#define SM_H (TILE_H + 6)   // 38
#define SM_W 136            // 134 needed, padded (544B rows, 16B aligned)

typedef unsigned long long u64;

__device__ __forceinline__ u64 pk(float a, float b) {
    u64 r;
    asm("mov.b64 %0, {%1, %2};" : "=l"(r) : "f"(a), "f"(b));
    return r;
}
__device__ __forceinline__ void upk(u64 v, float &a, float &b) {
    asm("mov.b64 {%0, %1}, %2;" : "=f"(a), "=f"(b) : "l"(v));
}
__device__ __forceinline__ void fma2(u64 &d, u64 a, u64 b) {
    asm("fma.rn.f32x2 %0, %1, %2, %3;" : "=l"(d) : "l"(a), "l"(b), "l"(d));
}

__global__ __launch_bounds__(256)
void conv7x7_kernel(const float* __restrict__ x,
                    const float* __restrict__ w,
                    const float* __restrict__ bias,
                    float* __restrict__ out)
{
    __shared__ float tile[SM_H][SM_W];
    __shared__ u64   wp[49];
    __shared__ float bs;

    const int tx = threadIdx.x;         // 0..15
    const int ty = threadIdx.y;         // 0..15
    const int tid = ty * 16 + tx;       // 0..255

    const int bx = blockIdx.x * TILE_W;
    const int by = blockIdx.y * TILE_H;

    if (tid < 49) { float wv = w[tid]; wp[tid] = pk(wv, wv); }
    if (tid == 49) bs = bias[0];

    // ---- Load input tile (38 x 136 floats, float4 granularity) ----
    #pragma unroll 1
    for (int i = tid; i < SM_H * (SM_W / 4); i += 256) {
        const int r  = i / (SM_W / 4);
        const int c4 = i - r * (SM_W / 4);
        const int gy = by + r;
        const int gx = bx + c4 * 4;
        float4 v = make_float4(0.f, 0.f, 0.f, 0.f);
        if (gy < IN_H) {
            const float* row = x + (size_t)gy * IN_W;
            if (gx + 4 <= IN_W) {
                v = *reinterpret_cast<const float4*>(row + gx);
            } else if (gx < IN_W) {
                v.x = row[gx];
                if (gx + 1 < IN_W) v.y = row[gx + 1];
                if (gx + 2 < IN_W) v.z = row[gx + 2];
            }
        }
        *reinterpret_cast<float4*>(&tile[r][c4 * 4]) = v;
    }
    __syncthreads();

    // ---- Compute: 2 output rows x 8 cols per thread ----
    const int tx8 = tx * 8;        // col base within tile (32B-aligned)
    const int ry  = ty * 2;        // first output row within tile

    // accE[ar][v]: (out[2v],   out[2v+1]) even-dx partials, v=0..3
    // accO[ar][v]: (out[2v-1], out[2v]  ) odd-dx partials,  v=0..4 (edge lanes garbage)
    u64 accE[2][4];
    u64 accO[2][5];
    #pragma unroll
    for (int a = 0; a < 2; a++) {
        #pragma unroll
        for (int v = 0; v < 4; v++) accE[a][v] = 0ull;
        #pragma unroll
        for (int v = 0; v < 5; v++) accO[a][v] = 0ull;
    }

    // kr-major: hoist weight row kr into registers once, use for both acc rows.
    #pragma unroll
    for (int kr = 0; kr < 7; kr++) {
        u64 wrow[7];
        #pragma unroll
        for (int j = 0; j < 7; j++) wrow[j] = wp[kr * 7 + j];

        #pragma unroll
        for (int ar = 0; ar < 2; ar++) {
            const int r = kr + ar;          // input row offset: ry + r
            u64 E[8];                        // E[m] = (seg[2m], seg[2m+1])
            {
                const ulonglong2* srow =
                    reinterpret_cast<const ulonglong2*>(&tile[ry + r][tx8]);
                ulonglong2 q0 = srow[0];
                ulonglong2 q1 = srow[1];
                ulonglong2 q2 = srow[2];
                ulonglong2 q3 = srow[3];
                E[0] = q0.x; E[1] = q0.y;
                E[2] = q1.x; E[3] = q1.y;
                E[4] = q2.x; E[5] = q2.y;
                E[6] = q3.x; E[7] = q3.y;
            }
            // even dx
            #pragma unroll
            for (int dx = 0; dx <= 6; dx += 2) {
                #pragma unroll
                for (int v = 0; v < 4; v++)
                    fma2(accE[ar][v], E[v + dx / 2], wrow[dx]);
            }
            // odd dx
            #pragma unroll
            for (int dx = 1; dx <= 5; dx += 2) {
                #pragma unroll
                for (int v = 0; v < 5; v++)
                    fma2(accO[ar][v], E[v + (dx - 1) / 2], wrow[dx]);
            }
        }
    }

    // ---- Epilogue: recombine even/odd partials, add bias, store float2 ----
    const float bv = bs;
    #pragma unroll
    for (int ar = 0; ar < 2; ar++) {
        const int oy = by + ry + ar;
        if (oy < OUT_H) {
            float* orow = out + (size_t)oy * OUT_W;
            #pragma unroll
            for (int v = 0; v < 4; v++) {
                const int ox = bx + tx8 + 2 * v;
                if (ox < OUT_W) {
                    float eL, eH, oLoA, oHiA, oLoB, oHiB;
                    upk(accE[ar][v],     eL,   eH);
                    upk(accO[ar][v],     oLoA, oHiA);
                    upk(accO[ar][v + 1], oLoB, oHiB);
                    float2 o;
                    o.x = eL + oHiA + bv;   // out[2v]
                    o.y = eH + oLoB + bv;   // out[2v+1]
                    *reinterpret_cast<float2*>(orow + ox) = o;
                }
            }
        }
    }
}

extern "C" void kernel_launch(void* const* d_in, const int* in_sizes, int n_in,
                              void* d_out, int out_size)
{
    const float* x    = (const float*)d_in[0];
    const float* w    = (const float*)d_in[1];
    const float* bias = (const float*)d_in[2];
    float* out = (float*)d_out;

    dim3 block(16, 16);
    dim3 grid((OUT_W + TILE_W - 1) / TILE_W,   // 32
              (OUT_H + TILE_H - 1) / TILE_H);  // 128
    conv7x7_kernel<<<grid, block>>>(x, w, bias, out);
}

// round 6
// speedup vs baseline: 1.3002x; 1.2767x over previous
#include <cuda_runtime.h>
#include <cstddef>

// 7x7 VALID conv, 4096x4096 fp32 -> 4090x4090 fp32, + bias.
// Block 16x8 = 128 threads; tile 128(w) x 32(h); thread: 4 rows x 8 cols.
// Packed fma.rn.f32x2, single accumulator family (zero FMA waste: 24.5 fma2/out).
// Odd-tap operand pairs built in registers: S[m] = (hi(E[m]), lo(E[m+1])).
// r-major loop: each input row loaded once (4 LDS); weight rows padded to 64B
// and fetched with 4 broadcast loads per (r,kr) group.

#define IN_W 4096
#define IN_H 4096
#define OUT_W 4090
#define OUT_H 4090

#define TILE_W 128
#define TILE_H 32
#define SM_H (TILE_H + 6)   // 38
#define SM_W 136            // 134 needed, padded (544B rows, 16B aligned)

typedef unsigned long long u64;

__device__ __forceinline__ u64 pk(float a, float b) {
    u64 r;
    asm("mov.b64 %0, {%1, %2};" : "=l"(r) : "f"(a), "f"(b));
    return r;
}
__device__ __forceinline__ void upk(u64 v, float &a, float &b) {
    asm("mov.b64 {%0, %1}, %2;" : "=f"(a), "=f"(b) : "l"(v));
}
__device__ __forceinline__ void fma2(u64 &d, u64 a, u64 b) {
    asm("fma.rn.f32x2 %0, %1, %2, %3;" : "=l"(d) : "l"(a), "l"(b), "l"(d));
}
__device__ __forceinline__ u64 add2(u64 a, u64 b) {
    u64 r;
    asm("add.rn.f32x2 %0, %1, %2;" : "=l"(r) : "l"(a), "l"(b));
    return r;
}

__global__ __launch_bounds__(128)
void conv7x7_kernel(const float* __restrict__ x,
                    const float* __restrict__ w,
                    const float* __restrict__ bias,
                    float* __restrict__ out)
{
    __shared__ float tile[SM_H][SM_W];
    __shared__ u64   wp[7][8];      // weight rows padded to 64B for LDS.128
    __shared__ float bs;

    const int tx = threadIdx.x;     // 0..15
    const int ty = threadIdx.y;     // 0..7
    const int tid = ty * 16 + tx;   // 0..127

    const int bx = blockIdx.x * TILE_W;
    const int by = blockIdx.y * TILE_H;

    if (tid < 49) {
        const int r = tid / 7, c = tid % 7;
        float wv = w[tid];
        wp[r][c] = pk(wv, wv);
    }
    if (tid == 49) bs = bias[0];

    // ---- Load input tile (38 x 136 floats, float4 granularity) ----
    #pragma unroll 1
    for (int i = tid; i < SM_H * (SM_W / 4); i += 128) {
        const int r  = i / (SM_W / 4);
        const int c4 = i - r * (SM_W / 4);
        const int gy = by + r;
        const int gx = bx + c4 * 4;
        float4 v = make_float4(0.f, 0.f, 0.f, 0.f);
        if (gy < IN_H) {
            const float* row = x + (size_t)gy * IN_W;
            if (gx + 4 <= IN_W) {
                v = *reinterpret_cast<const float4*>(row + gx);
            } else if (gx < IN_W) {
                v.x = row[gx];
                if (gx + 1 < IN_W) v.y = row[gx + 1];
                if (gx + 2 < IN_W) v.z = row[gx + 2];
            }
        }
        *reinterpret_cast<float4*>(&tile[r][c4 * 4]) = v;
    }
    __syncthreads();

    // ---- Compute: 4 output rows x 8 cols per thread ----
    const int tx8 = tx * 8;         // col base (32B-aligned in smem)
    const int ry  = ty * 4;         // first output row within tile

    // acc[ar][v] = (out[2v], out[2v+1]) for output row ry+ar
    u64 acc[4][4];
    #pragma unroll
    for (int a = 0; a < 4; a++)
        #pragma unroll
        for (int v = 0; v < 4; v++) acc[a][v] = 0ull;

    #pragma unroll
    for (int r = 0; r < 10; r++) {
        // E[m] = (seg[2m], seg[2m+1]), m=0..6  (seg = tile[ry+r][tx8 + .])
        u64 E[7];
        {
            const ulonglong2* s2 =
                reinterpret_cast<const ulonglong2*>(&tile[ry + r][tx8]);
            ulonglong2 q0 = s2[0];
            ulonglong2 q1 = s2[1];
            ulonglong2 q2 = s2[2];
            E[0] = q0.x; E[1] = q0.y;
            E[2] = q1.x; E[3] = q1.y;
            E[4] = q2.x; E[5] = q2.y;
            E[6] = *reinterpret_cast<const u64*>(&tile[ry + r][tx8 + 12]);
        }
        // S[m] = (seg[2m+1], seg[2m+2]) = (hi(E[m]), lo(E[m+1])), m=0..5
        u64 S[6];
        #pragma unroll
        for (int m = 0; m < 6; m++) {
            float eh, el_dummy, el1, eh1_dummy;
            upk(E[m],     el_dummy, eh);     // halves are free (register aliases)
            upk(E[m + 1], el1,      eh1_dummy);
            S[m] = pk(eh, el1);              // 2 MOVs
        }

        #pragma unroll
        for (int ar = 0; ar < 4; ar++) {
            const int kr = r - ar;
            if (kr >= 0 && kr <= 6) {
                // weight row kr: 3x LDS.128 + 1x LDS.64, all broadcast
                u64 wr[7];
                {
                    const ulonglong2* w2 =
                        reinterpret_cast<const ulonglong2*>(&wp[kr][0]);
                    ulonglong2 a0 = w2[0];
                    ulonglong2 a1 = w2[1];
                    ulonglong2 a2 = w2[2];
                    wr[0] = a0.x; wr[1] = a0.y;
                    wr[2] = a1.x; wr[3] = a1.y;
                    wr[4] = a2.x; wr[5] = a2.y;
                    wr[6] = wp[kr][6];
                }
                // even taps: acc[v] += E[v + dx/2] * w
                #pragma unroll
                for (int dx = 0; dx <= 6; dx += 2) {
                    #pragma unroll
                    for (int v = 0; v < 4; v++)
                        fma2(acc[ar][v], E[v + dx / 2], wr[dx]);
                }
                // odd taps: acc[v] += S[v + (dx-1)/2] * w
                #pragma unroll
                for (int dx = 1; dx <= 5; dx += 2) {
                    #pragma unroll
                    for (int v = 0; v < 4; v++)
                        fma2(acc[ar][v], S[v + (dx - 1) / 2], wr[dx]);
                }
            }
        }
    }

    // ---- Epilogue: packed bias add, float2 stores ----
    const float bv = bs;
    const u64 bp = pk(bv, bv);
    #pragma unroll
    for (int ar = 0; ar < 4; ar++) {
        const int oy = by + ry + ar;
        if (oy < OUT_H) {
            float* orow = out + (size_t)oy * OUT_W;
            #pragma unroll
            for (int v = 0; v < 4; v++) {
                const int ox = bx + tx8 + 2 * v;
                if (ox < OUT_W) {
                    u64 o = add2(acc[ar][v], bp);
                    *reinterpret_cast<u64*>(orow + ox) = o;  // 8B-aligned
                }
            }
        }
    }
}

extern "C" void kernel_launch(void* const* d_in, const int* in_sizes, int n_in,
                              void* d_out, int out_size)
{
    const float* x    = (const float*)d_in[0];
    const float* w    = (const float*)d_in[1];
    const float* bias = (const float*)d_in[2];
    float* out = (float*)d_out;

    dim3 block(16, 8);
    dim3 grid((OUT_W + TILE_W - 1) / TILE_W,   // 32
              (OUT_H + TILE_H - 1) / TILE_H);  // 128
    conv7x7_kernel<<<grid, block>>>(x, w, bias, out);
}